// round 15
// baseline (speedup 1.0000x reference)
#include <cuda_runtime.h>
#include <cuda_bf16.h>
#include <cstdint>
#include <cstddef>

#define BATCH 64
#define NSENT 1024
#define NENT  256
#define DIM   512
#define NEGV  (-1e9f)
#define WSCALE 16.0f
#define SCI    0.0625f

// ---------------- device scratch --------------------------------------------
__device__ __align__(16) uint8_t g_wt8[2][16][512][32];      // fp8 W^T, pair-interleaved k
__device__ __align__(16) float g_wqt[3][DIM * DIM];          // transposed fp32 wq/ws
__device__ float g_query[BATCH * DIM];
__device__ float g_qs[BATCH * DIM];
__device__ float g_qa[BATCH * DIM];
__device__ float g_ctx[BATCH * DIM];
__device__ float g_bias[BATCH * DIM];
__device__ float g_attn[BATCH * NENT];
__device__ __align__(16) __nv_bfloat162 g_sidefeat[(size_t)BATCH * NENT * DIM / 2];
__device__ float g_escore_part[4 * BATCH * NENT];
__device__ float g_score_part[4 * BATCH * NSENT];

// ---- dynamic SMEM layout for gemm (bytes) ----
#define FSTR   144
#define FSTG   18432            // fp32 A staging: 128 rows x 144B
#define SM_A8  0                // 2 x 4096 (fp8 A tile, 128 rows x 32B)
#define SM_B8  8192             // 2 x 4096 (fp8 B tile)
#define SM_F   16384            // 2 x FSTG
#define SM_BI  53248
#define SM_V   53760
#define SM_P   54272            // 128*4 floats
#define SM_TOT 56320

// ---------------- helpers ----------------------------------------------------
__device__ __forceinline__ uint32_t smem_u32(const void* p) {
    uint32_t a;
    asm("{ .reg .u64 t; cvta.to.shared.u64 t, %1; cvt.u32.u64 %0, t; }" : "=r"(a) : "l"(p));
    return a;
}
__device__ __forceinline__ void cp16(uint32_t dst, const void* src) {
    asm volatile("cp.async.cg.shared.global [%0], [%1], 16;" :: "r"(dst), "l"(src));
}
__device__ __forceinline__ void lds64(uint32_t& x, uint32_t& y, uint32_t a) {
    asm volatile("ld.shared.v2.u32 {%0,%1}, [%2];" : "=r"(x), "=r"(y) : "r"(a));
}
__device__ __forceinline__ void mma_fp8(float* c, uint32_t a0, uint32_t a1, uint32_t a2,
                                        uint32_t a3, uint32_t b0, uint32_t b1) {
    asm volatile("mma.sync.aligned.m16n8k32.row.col.f32.e4m3.e4m3.f32 "
                 "{%0,%1,%2,%3}, {%4,%5,%6,%7}, {%8,%9}, {%0,%1,%2,%3};"
                 : "+f"(c[0]), "+f"(c[1]), "+f"(c[2]), "+f"(c[3])
                 : "r"(a0), "r"(a1), "r"(a2), "r"(a3), "r"(b0), "r"(b1));
}
// pack 4 floats to 4 e4m3 bytes (byte0 = a, byte1 = b, byte2 = c, byte3 = d)
__device__ __forceinline__ uint32_t pack4_e4m3(float a, float b, float c, float d) {
    uint16_t lo, hi;
    asm("cvt.rn.satfinite.e4m3x2.f32 %0, %1, %2;" : "=h"(lo) : "f"(b), "f"(a));
    asm("cvt.rn.satfinite.e4m3x2.f32 %0, %1, %2;" : "=h"(hi) : "f"(d), "f"(c));
    return (uint32_t)lo | ((uint32_t)hi << 16);
}
__device__ __forceinline__ float tanh_fast(float x) {
    float e, r;
    asm("ex2.approx.f32 %0, %1;" : "=f"(e) : "f"(x * 2.8853900817779268f));
    asm("rcp.approx.f32 %0, %1;" : "=f"(r) : "f"(e + 1.f));
    return 1.f - 2.f * r;
}
__device__ __forceinline__ float sigmoidf_(float x) { return 1.f / (1.f + expf(-x)); }
__device__ __forceinline__ float warp_sum(float v) {
    #pragma unroll
    for (int o = 16; o; o >>= 1) v += __shfl_xor_sync(0xffffffffu, v, o);
    return v;
}
__device__ __forceinline__ __nv_bfloat162 bfp(float a, float b) {
    return __nv_bfloat162{__float2bfloat16(a), __float2bfloat16(b)};
}

// ------ prepack W: W[k][n] fp32 -> fp8 Wt8[mode][kc][n][32B interleaved], x16 ----
__global__ void prepack_w8(const float* __restrict__ w0, const float* __restrict__ w1) {
    __shared__ float t[32][33];
    const float* src = blockIdx.z ? w1 : w0;
    int tx = threadIdx.x, ty = threadIdx.y;
    int k0 = blockIdx.x * 32, n0 = blockIdx.y * 32;
    t[ty][tx] = src[(size_t)(k0 + ty) * DIM + n0 + tx] * WSCALE;
    __syncthreads();
    if (tx < 8) {
        int kl = ((tx >> 1) << 2) | ((tx & 1) << 4);   // pair-interleave
        uint32_t p = pack4_e4m3(t[kl][ty], t[kl + 1][ty], t[kl + 2][ty], t[kl + 3][ty]);
        *(uint32_t*)&g_wt8[blockIdx.z][blockIdx.x][n0 + ty][tx * 4] = p;
    }
}

// ---------------- prepack small W^T fp32 (wq_side, wq_attn, ws) --------------
__global__ void prepack_wt(const float* __restrict__ w0, const float* __restrict__ w1,
                           const float* __restrict__ w2) {
    __shared__ float t[32][33];
    const float* src = (blockIdx.z == 0) ? w0 : (blockIdx.z == 1) ? w1 : w2;
    float* dst = g_wqt[blockIdx.z];
    int tx = threadIdx.x, ty = threadIdx.y;
    int k0 = blockIdx.x * 32, n0 = blockIdx.y * 32;
    t[ty][tx] = src[(size_t)(k0 + ty) * DIM + n0 + tx];
    __syncthreads();
    dst[(size_t)(n0 + ty) * DIM + k0 + tx] = t[tx][ty];
}

// ---------------- fp8 mma GEMM, fused fp32->fp8 convert + tanh-reduce --------
// Grid: (n_tiles fastest, m_tiles, batch) for L2 A reuse.
template <int MODE>
__global__ void __launch_bounds__(256, 2)
gemm_mma(const float* __restrict__ A, const float* __restrict__ vvec) {
    constexpr int R = (MODE == 0) ? NENT : NSENT;
    extern __shared__ __align__(16) char smem[];
    float* bias_s = (float*)(smem + SM_BI);
    float* v_s    = (float*)(smem + SM_V);
    float* sPart  = (float*)(smem + SM_P);

    int tid = threadIdx.x, lane = tid & 31, wid = tid >> 5;
    int warp_m = wid >> 2, warp_n = wid & 3;
    int n0 = blockIdx.x * 128, m0 = blockIdx.y * 128, b = blockIdx.z;

    const float* Ab = A + ((size_t)b * R + m0) * DIM;
    const float* bias = ((MODE == 0) ? g_qs : g_bias) + b * DIM + n0;
    if (tid < 128) { bias_s[tid] = bias[tid]; v_s[tid] = vvec[n0 + tid]; }

    const uint32_t sA8 = smem_u32(smem + SM_A8), sB8 = smem_u32(smem + SM_B8);
    const uint32_t sF  = smem_u32(smem + SM_F);

    auto load_stage = [&](int kc, int st) {
        uint32_t df = sF + st * FSTG;
        const float* ak = Ab + kc * 32;
        #pragma unroll
        for (int i = 0; i < 4; i++) {
            int u = tid + i * 256, r = u >> 3, c = u & 7;
            cp16(df + r * FSTR + c * 16, ak + (size_t)r * DIM + c * 4);
        }
        const uint8_t* wk = &g_wt8[MODE][kc][n0][0];
        cp16(sB8 + st * 4096 + tid * 16, wk + tid * 16);
        asm volatile("cp.async.commit_group;" ::: "memory");
    };
    auto convert = [&](int st) {   // fp32 staging -> fp8 pair-interleaved A tile
        int r = tid >> 1, h = tid & 1;
        const char* sg = smem + SM_F + st * FSTG + r * FSTR + h * 64;
        float4 x0 = *(const float4*)(sg);
        float4 x1 = *(const float4*)(sg + 16);
        float4 x2 = *(const float4*)(sg + 32);
        float4 x3 = *(const float4*)(sg + 48);
        char* d = smem + SM_A8 + st * 4096 + r * 32 + h * 4;
        *(uint32_t*)(d)      = pack4_e4m3(x0.x, x0.y, x0.z, x0.w);
        *(uint32_t*)(d + 8)  = pack4_e4m3(x1.x, x1.y, x1.z, x1.w);
        *(uint32_t*)(d + 16) = pack4_e4m3(x2.x, x2.y, x2.z, x2.w);
        *(uint32_t*)(d + 24) = pack4_e4m3(x3.x, x3.y, x3.z, x3.w);
    };

    float c[4][4][4];
    #pragma unroll
    for (int i = 0; i < 4; i++)
        #pragma unroll
        for (int j = 0; j < 4; j++)
            #pragma unroll
            for (int q = 0; q < 4; q++) c[i][j][q] = 0.f;

    uint32_t aBase = sA8 + (warp_m * 64 + (lane >> 2)) * 32 + (lane & 3) * 8;
    uint32_t bBase = sB8 + (warp_n * 32 + (lane >> 2)) * 32 + (lane & 3) * 8;

    load_stage(0, 0);
    #pragma unroll 1
    for (int kc = 0; kc < 16; kc++) {
        int cur = kc & 1;
        asm volatile("cp.async.wait_group 0;" ::: "memory");
        __syncthreads();
        convert(cur);
        __syncthreads();
        if (kc < 15) load_stage(kc + 1, cur ^ 1);

        uint32_t af[4][4], bf[4][2];
        #pragma unroll
        for (int mf = 0; mf < 4; mf++) {
            uint32_t base = aBase + cur * 4096 + mf * 512;
            lds64(af[mf][0], af[mf][2], base);
            lds64(af[mf][1], af[mf][3], base + 256);
        }
        #pragma unroll
        for (int nf = 0; nf < 4; nf++)
            lds64(bf[nf][0], bf[nf][1], bBase + cur * 4096 + nf * 256);
        #pragma unroll
        for (int mf = 0; mf < 4; mf++)
            #pragma unroll
            for (int nf = 0; nf < 4; nf++)
                mma_fp8(c[mf][nf], af[mf][0], af[mf][1], af[mf][2], af[mf][3],
                        bf[nf][0], bf[nf][1]);
    }
    __syncthreads();

    int qr = lane >> 2, qc = lane & 3;
    #pragma unroll
    for (int mf = 0; mf < 4; mf++) {
        int r0 = warp_m * 64 + mf * 16 + qr;
        int r1 = r0 + 8;
        float s0 = 0.f, s1 = 0.f;
        #pragma unroll
        for (int nf = 0; nf < 4; nf++) {
            int nl = warp_n * 32 + nf * 8 + qc * 2;
            float f0 = c[mf][nf][0] * SCI, f1 = c[mf][nf][1] * SCI;
            float f2 = c[mf][nf][2] * SCI, f3 = c[mf][nf][3] * SCI;
            if (MODE == 0) {
                size_t base = ((size_t)b * NENT + m0) * (DIM / 2) + (n0 + nl) / 2;
                g_sidefeat[base + (size_t)r0 * (DIM / 2)] = bfp(f0, f1);
                g_sidefeat[base + (size_t)r1 * (DIM / 2)] = bfp(f2, f3);
            }
            s0 += tanh_fast(f0 + bias_s[nl]) * v_s[nl] + tanh_fast(f1 + bias_s[nl + 1]) * v_s[nl + 1];
            s1 += tanh_fast(f2 + bias_s[nl]) * v_s[nl] + tanh_fast(f3 + bias_s[nl + 1]) * v_s[nl + 1];
        }
        s0 += __shfl_xor_sync(0xffffffffu, s0, 1);
        s0 += __shfl_xor_sync(0xffffffffu, s0, 2);
        s1 += __shfl_xor_sync(0xffffffffu, s1, 1);
        s1 += __shfl_xor_sync(0xffffffffu, s1, 2);
        if (qc == 0) { sPart[r0 * 4 + warp_n] = s0; sPart[r1 * 4 + warp_n] = s1; }
    }
    __syncthreads();
    if (tid < 128) {
        float s = sPart[tid * 4] + sPart[tid * 4 + 1] + sPart[tid * 4 + 2] + sPart[tid * 4 + 3];
        float* spart = (MODE == 0) ? g_escore_part : g_score_part;
        spart[((size_t)blockIdx.x * BATCH + b) * R + m0 + tid] = s;
    }
}

// ---------------- LSTM: block = 8 h, loop all 64 b (W read once) -------------
__global__ void lstm_kernel(const float* __restrict__ x, const float* __restrict__ wih,
                            const float* __restrict__ bih, const float* __restrict__ bhh) {
    __shared__ float xT[64][65];
    __shared__ float wrow[3][8][64];
    int tid = threadIdx.x, wid = tid >> 5, lane = tid & 31;
    int h = blockIdx.x * 8 + wid;
    float ai[2] = {0.f, 0.f}, ag[2] = {0.f, 0.f}, ao[2] = {0.f, 0.f};
    #pragma unroll 1
    for (int cb = 0; cb < 8; cb++) {
        int k0 = cb * 64;
        __syncthreads();
        #pragma unroll
        for (int i = 0; i < 4; i++) {
            int bb = tid >> 2, kv = (tid & 3) + 4 * i;
            float4 v = *(const float4*)&x[bb * DIM + k0 + kv * 4];
            xT[kv * 4 + 0][bb] = v.x; xT[kv * 4 + 1][bb] = v.y;
            xT[kv * 4 + 2][bb] = v.z; xT[kv * 4 + 3][bb] = v.w;
        }
        #pragma unroll
        for (int i = 0; i < 6; i++) {
            int idx = tid + i * 256;
            int g = idx >> 9, rem = idx & 511, hh = rem >> 6, kk = rem & 63;
            int grow = (g == 0) ? 0 : (g == 1 ? 2 : 3);
            wrow[g][hh][kk] = wih[(size_t)(grow * 512 + blockIdx.x * 8 + hh) * DIM + k0 + kk];
        }
        __syncthreads();
        #pragma unroll 16
        for (int kk = 0; kk < 64; kk++) {
            float x0 = xT[kk][lane], x1 = xT[kk][lane + 32];
            float wi_ = wrow[0][wid][kk], wg_ = wrow[1][wid][kk], wo_ = wrow[2][wid][kk];
            ai[0] = fmaf(wi_, x0, ai[0]); ai[1] = fmaf(wi_, x1, ai[1]);
            ag[0] = fmaf(wg_, x0, ag[0]); ag[1] = fmaf(wg_, x1, ag[1]);
            ao[0] = fmaf(wo_, x0, ao[0]); ao[1] = fmaf(wo_, x1, ao[1]);
        }
    }
    float bi = bih[h] + bhh[h];
    float bg = bih[1024 + h] + bhh[1024 + h];
    float bo = bih[1536 + h] + bhh[1536 + h];
    #pragma unroll
    for (int j = 0; j < 2; j++) {
        int bb = lane + 32 * j;
        float ii = sigmoidf_(ai[j] + bi);
        float gg = tanhf(ag[j] + bg);
        float oo = sigmoidf_(ao[j] + bo);
        g_query[bb * DIM + h] = oo * tanhf(ii * gg);
    }
}

// ---------------- proj01: block = (8 h, mode), loop all 64 b -----------------
__global__ void proj01_kernel() {
    __shared__ float xT[64][65];
    __shared__ float wrow[8][64];
    int tid = threadIdx.x, wid = tid >> 5, lane = tid & 31;
    int mode = blockIdx.y;
    int h = blockIdx.x * 8 + wid;
    const float* W = g_wqt[mode];
    float acc[2] = {0.f, 0.f};
    #pragma unroll 1
    for (int cb = 0; cb < 8; cb++) {
        int k0 = cb * 64;
        __syncthreads();
        #pragma unroll
        for (int i = 0; i < 4; i++) {
            int bb = tid >> 2, kv = (tid & 3) + 4 * i;
            float4 v = *(const float4*)&g_query[bb * DIM + k0 + kv * 4];
            xT[kv * 4 + 0][bb] = v.x; xT[kv * 4 + 1][bb] = v.y;
            xT[kv * 4 + 2][bb] = v.z; xT[kv * 4 + 3][bb] = v.w;
        }
        #pragma unroll
        for (int i = 0; i < 2; i++) {
            int idx = tid + i * 256;
            int hh = idx >> 6, kk = idx & 63;
            wrow[hh][kk] = W[(size_t)(blockIdx.x * 8 + hh) * DIM + k0 + kk];
        }
        __syncthreads();
        #pragma unroll 16
        for (int kk = 0; kk < 64; kk++) {
            float w = wrow[wid][kk];
            acc[0] = fmaf(w, xT[kk][lane], acc[0]);
            acc[1] = fmaf(w, xT[kk][lane + 32], acc[1]);
        }
    }
    float* out = (mode == 0) ? g_qs : g_qa;
    out[lane * DIM + h] = acc[0];
    out[(lane + 32) * DIM + h] = acc[1];
}

// ---------------- proj2: bias = qa + ctx @ ws --------------------------------
__global__ void proj2_kernel() {
    __shared__ float xT[64][65];
    __shared__ float wrow[8][64];
    int tid = threadIdx.x, wid = tid >> 5, lane = tid & 31;
    int h = blockIdx.x * 8 + wid;
    const float* W = g_wqt[2];
    float acc[2] = {0.f, 0.f};
    #pragma unroll 1
    for (int cb = 0; cb < 8; cb++) {
        int k0 = cb * 64;
        __syncthreads();
        #pragma unroll
        for (int i = 0; i < 4; i++) {
            int bb = tid >> 2, kv = (tid & 3) + 4 * i;
            float4 v = *(const float4*)&g_ctx[bb * DIM + k0 + kv * 4];
            xT[kv * 4 + 0][bb] = v.x; xT[kv * 4 + 1][bb] = v.y;
            xT[kv * 4 + 2][bb] = v.z; xT[kv * 4 + 3][bb] = v.w;
        }
        #pragma unroll
        for (int i = 0; i < 2; i++) {
            int idx = tid + i * 256;
            int hh = idx >> 6, kk = idx & 63;
            wrow[hh][kk] = W[(size_t)(blockIdx.x * 8 + hh) * DIM + k0 + kk];
        }
        __syncthreads();
        #pragma unroll 16
        for (int kk = 0; kk < 64; kk++) {
            float w = wrow[wid][kk];
            acc[0] = fmaf(w, xT[kk][lane], acc[0]);
            acc[1] = fmaf(w, xT[kk][lane + 32], acc[1]);
        }
    }
    g_bias[lane * DIM + h] = g_qa[lane * DIM + h] + acc[0];
    g_bias[(lane + 32) * DIM + h] = g_qa[(lane + 32) * DIM + h] + acc[1];
}

// ---------------- masked softmax over entities -> g_attn ---------------------
__global__ void softmax_kernel(const int* __restrict__ entity_nums) {
    int b = blockIdx.x, tid = threadIdx.x;
    __shared__ float red[8];
    int n = entity_nums[b];
    float v = g_escore_part[(0 * BATCH + b) * NENT + tid]
            + g_escore_part[(1 * BATCH + b) * NENT + tid]
            + g_escore_part[(2 * BATCH + b) * NENT + tid]
            + g_escore_part[(3 * BATCH + b) * NENT + tid];
    if (tid >= n) v = NEGV;
    float m = v;
    #pragma unroll
    for (int o = 16; o; o >>= 1) m = fmaxf(m, __shfl_xor_sync(0xffffffffu, m, o));
    if ((tid & 31) == 0) red[tid >> 5] = m;
    __syncthreads();
    float M = red[0];
    #pragma unroll
    for (int i = 1; i < 8; i++) M = fmaxf(M, red[i]);
    __syncthreads();
    float e = expf(v - M);
    float s = warp_sum(e);
    if ((tid & 31) == 0) red[tid >> 5] = s;
    __syncthreads();
    float S = red[0];
    #pragma unroll
    for (int i = 1; i < 8; i++) S += red[i];
    g_attn[b * NENT + tid] = e / S;
}

// ---------------- ctx from bf16 sidefeat -------------------------------------
__global__ void ctx_kernel() {
    int b = blockIdx.y;
    int h2 = blockIdx.x * 128 + threadIdx.x;
    __shared__ float attn[NENT];
    attn[threadIdx.x] = g_attn[b * NENT + threadIdx.x];
    attn[threadIdx.x + 128] = g_attn[b * NENT + 128 + threadIdx.x];
    __syncthreads();
    const __nv_bfloat162* fb = g_sidefeat + (size_t)b * NENT * (DIM / 2) + h2;
    float a0 = 0.f, a1 = 0.f;
    #pragma unroll 8
    for (int e = 0; e < NENT; e++) {
        __nv_bfloat162 f = fb[(size_t)e * (DIM / 2)];
        a0 = fmaf(attn[e], __bfloat162float(f.x), a0);
        a1 = fmaf(attn[e], __bfloat162float(f.y), a1);
    }
    g_ctx[b * DIM + 2 * h2]     = a0;
    g_ctx[b * DIM + 2 * h2 + 1] = a1;
}

// ---------------- finalize ----------------------------------------------------
__global__ void finalize_kernel(const int* __restrict__ sent_nums, float* __restrict__ out) {
    int i = blockIdx.x * 256 + threadIdx.x;
    int b = i >> 10, s = i & 1023;
    float v = g_score_part[(0 * BATCH + b) * NSENT + s]
            + g_score_part[(1 * BATCH + b) * NSENT + s]
            + g_score_part[(2 * BATCH + b) * NSENT + s]
            + g_score_part[(3 * BATCH + b) * NSENT + s];
    out[i] = (s < sent_nums[b]) ? v : NEGV;
}

// ---------------- launch ------------------------------------------------------
extern "C" void kernel_launch(void* const* d_in, const int* in_sizes, int n_in,
                              void* d_out, int out_size) {
    const float* sent_mem    = (const float*)d_in[0];
    const float* entity_mem  = (const float*)d_in[1];
    const float* ptr_in      = (const float*)d_in[2];
    const int*   sent_nums   = (const int*)d_in[3];
    const int*   entity_nums = (const int*)d_in[4];
    const float* lstm_w_ih   = (const float*)d_in[5];
    const float* lstm_b_ih   = (const float*)d_in[7];
    const float* lstm_b_hh   = (const float*)d_in[8];
    const float* attn_wm     = (const float*)d_in[9];
    const float* attn_wq     = (const float*)d_in[10];
    const float* attn_v      = (const float*)d_in[11];
    const float* side_wm     = (const float*)d_in[12];
    const float* side_wq     = (const float*)d_in[13];
    const float* side_v      = (const float*)d_in[14];
    const float* attn_ws     = (const float*)d_in[15];
    float* out = (float*)d_out;

    static bool attr_done = false;
    if (!attr_done) {
        cudaFuncSetAttribute(gemm_mma<0>, cudaFuncAttributeMaxDynamicSharedMemorySize, SM_TOT);
        cudaFuncSetAttribute(gemm_mma<1>, cudaFuncAttributeMaxDynamicSharedMemorySize, SM_TOT);
        attr_done = true;
    }

    prepack_w8<<<dim3(16, 16, 2), dim3(32, 32)>>>(side_wm, attn_wm);
    prepack_wt<<<dim3(16, 16, 3), dim3(32, 32)>>>(side_wq, attn_wq, attn_ws);
    lstm_kernel<<<64, 256>>>(ptr_in, lstm_w_ih, lstm_b_ih, lstm_b_hh);
    proj01_kernel<<<dim3(64, 2), 256>>>();
    gemm_mma<0><<<dim3(4, 2, BATCH), 256, SM_TOT>>>(entity_mem, side_v);
    softmax_kernel<<<BATCH, 256>>>(entity_nums);
    ctx_kernel<<<dim3(2, BATCH), 128>>>();
    proj2_kernel<<<64, 256>>>();
    gemm_mma<1><<<dim3(4, 8, BATCH), 256, SM_TOT>>>(sent_mem, attn_v);
    finalize_kernel<<<BATCH * NSENT / 256, 256>>>(sent_nums, out);
}

// round 16
// speedup vs baseline: 1.0573x; 1.0573x over previous
#include <cuda_runtime.h>
#include <cuda_bf16.h>
#include <cstdint>
#include <cstddef>

#define BATCH 64
#define NSENT 1024
#define NENT  256
#define DIM   512
#define NEGV  (-1e9f)
#define WSCALE 16.0f
#define SCI    0.0625f

// ---------------- device scratch --------------------------------------------
__device__ __align__(16) uint8_t g_wt8[2][16][512][32];   // fp8 W^T, pair-interleaved k
__device__ __align__(16) uint8_t g_sent8[(size_t)BATCH * NSENT * 512];  // fp8 A, frag layout
__device__ __align__(16) uint8_t g_ent8[(size_t)BATCH * NENT * 512];
__device__ __align__(16) float g_wqt[3][DIM * DIM];       // transposed fp32 wq/ws
__device__ float g_query[BATCH * DIM];
__device__ float g_qs[BATCH * DIM];
__device__ float g_qa[BATCH * DIM];
__device__ float g_ctx[BATCH * DIM];
__device__ float g_bias[BATCH * DIM];
__device__ float g_attn[BATCH * NENT];
__device__ __align__(16) __nv_bfloat162 g_sidefeat[(size_t)BATCH * NENT * DIM / 2];
__device__ float g_escore_part[4 * BATCH * NENT];
__device__ float g_score_part[4 * BATCH * NSENT];

// ---------------- helpers ----------------------------------------------------
__device__ __forceinline__ uint32_t smem_u32(const void* p) {
    uint32_t a;
    asm("{ .reg .u64 t; cvta.to.shared.u64 t, %1; cvt.u32.u64 %0, t; }" : "=r"(a) : "l"(p));
    return a;
}
__device__ __forceinline__ void cp16(uint32_t dst, const void* src) {
    asm volatile("cp.async.cg.shared.global [%0], [%1], 16;" :: "r"(dst), "l"(src));
}
__device__ __forceinline__ void lds64(uint32_t& x, uint32_t& y, uint32_t a) {
    asm volatile("ld.shared.v2.u32 {%0,%1}, [%2];" : "=r"(x), "=r"(y) : "r"(a));
}
__device__ __forceinline__ void mma_fp8(float* c, uint32_t a0, uint32_t a1, uint32_t a2,
                                        uint32_t a3, uint32_t b0, uint32_t b1) {
    asm volatile("mma.sync.aligned.m16n8k32.row.col.f32.e4m3.e4m3.f32 "
                 "{%0,%1,%2,%3}, {%4,%5,%6,%7}, {%8,%9}, {%0,%1,%2,%3};"
                 : "+f"(c[0]), "+f"(c[1]), "+f"(c[2]), "+f"(c[3])
                 : "r"(a0), "r"(a1), "r"(a2), "r"(a3), "r"(b0), "r"(b1));
}
__device__ __forceinline__ uint32_t pack4_e4m3(float a, float b, float c, float d) {
    uint16_t lo, hi;
    asm("cvt.rn.satfinite.e4m3x2.f32 %0, %1, %2;" : "=h"(lo) : "f"(b), "f"(a));
    asm("cvt.rn.satfinite.e4m3x2.f32 %0, %1, %2;" : "=h"(hi) : "f"(d), "f"(c));
    return (uint32_t)lo | ((uint32_t)hi << 16);
}
__device__ __forceinline__ float tanh_fast(float x) {
    float e, r;
    asm("ex2.approx.f32 %0, %1;" : "=f"(e) : "f"(x * 2.8853900817779268f));
    asm("rcp.approx.f32 %0, %1;" : "=f"(r) : "f"(e + 1.f));
    return 1.f - 2.f * r;
}
__device__ __forceinline__ float sigmoidf_(float x) { return 1.f / (1.f + expf(-x)); }
__device__ __forceinline__ float warp_sum(float v) {
    #pragma unroll
    for (int o = 16; o; o >>= 1) v += __shfl_xor_sync(0xffffffffu, v, o);
    return v;
}
__device__ __forceinline__ __nv_bfloat162 bfp(float a, float b) {
    return __nv_bfloat162{__float2bfloat16(a), __float2bfloat16(b)};
}

// ------ cvt A: fp32 [rows, 512] -> fp8 frag-interleaved [rows, 16 chunks, 32B] --
// Per-row-chunk byte layout: [k0-3][k16-19][k4-7][k20-23][k8-11][k24-27][k12-15][k28-31]
__global__ void cvt_a8(const float* __restrict__ src, uint8_t* __restrict__ dst) {
    int idx = blockIdx.x * 256 + threadIdx.x;
    int row = idx >> 4, kc = idx & 15;
    const float* s = src + (size_t)row * 512 + kc * 32;
    float x[32];
    #pragma unroll
    for (int j = 0; j < 8; j++) *(float4*)&x[4 * j] = *(const float4*)(s + 4 * j);
    uint32_t o[8];
    #pragma unroll
    for (int g = 0; g < 4; g++) {
        o[2 * g]     = pack4_e4m3(x[4 * g],      x[4 * g + 1],  x[4 * g + 2],  x[4 * g + 3]);
        o[2 * g + 1] = pack4_e4m3(x[16 + 4 * g], x[17 + 4 * g], x[18 + 4 * g], x[19 + 4 * g]);
    }
    uint8_t* d = dst + (size_t)row * 512 + kc * 32;
    *(uint4*)d        = *(uint4*)&o[0];
    *(uint4*)(d + 16) = *(uint4*)&o[4];
}

// ------ prepack W: W[k][n] fp32 -> fp8 Wt8[mode][kc][n][32B interleaved], x16 ----
__global__ void prepack_w8(const float* __restrict__ w0, const float* __restrict__ w1) {
    __shared__ float t[32][33];
    const float* src = blockIdx.z ? w1 : w0;
    int tx = threadIdx.x, ty = threadIdx.y;
    int k0 = blockIdx.x * 32, n0 = blockIdx.y * 32;
    t[ty][tx] = src[(size_t)(k0 + ty) * DIM + n0 + tx] * WSCALE;
    __syncthreads();
    if (tx < 8) {
        int kl = ((tx >> 1) << 2) | ((tx & 1) << 4);   // pair-interleave
        uint32_t p = pack4_e4m3(t[kl][ty], t[kl + 1][ty], t[kl + 2][ty], t[kl + 3][ty]);
        *(uint32_t*)&g_wt8[blockIdx.z][blockIdx.x][n0 + ty][tx * 4] = p;
    }
}

// ---------------- prepack small W^T fp32 (wq_side, wq_attn, ws) --------------
__global__ void prepack_wt(const float* __restrict__ w0, const float* __restrict__ w1,
                           const float* __restrict__ w2) {
    __shared__ float t[32][33];
    const float* src = (blockIdx.z == 0) ? w0 : (blockIdx.z == 1) ? w1 : w2;
    float* dst = g_wqt[blockIdx.z];
    int tx = threadIdx.x, ty = threadIdx.y;
    int k0 = blockIdx.x * 32, n0 = blockIdx.y * 32;
    t[ty][tx] = src[(size_t)(k0 + ty) * DIM + n0 + tx];
    __syncthreads();
    dst[(size_t)(n0 + ty) * DIM + k0 + tx] = t[tx][ty];
}

// ---------------- fp8 mma GEMM (pre-converted A), 4-stage pipeline -----------
// Grid: (n_tiles=4 fastest, m_tiles, batch). 1 sync per chunk, no convert.
template <int MODE>
__global__ void __launch_bounds__(256, 2)
gemm_mma(const float* __restrict__ vvec) {
    constexpr int R = (MODE == 0) ? NENT : NSENT;
    __shared__ __align__(16) uint8_t sA8[4][4096];
    __shared__ __align__(16) uint8_t sB8[4][4096];
    __shared__ float bias_s[128], v_s[128];
    __shared__ float sPart[128 * 4];

    int tid = threadIdx.x, lane = tid & 31, wid = tid >> 5;
    int warp_m = wid >> 2, warp_n = wid & 3;
    int n0 = blockIdx.x * 128, m0 = blockIdx.y * 128, b = blockIdx.z;

    const uint8_t* Ab = (MODE == 0 ? g_ent8 : g_sent8) + ((size_t)b * R + m0) * 512;
    const float* bias = ((MODE == 0) ? g_qs : g_bias) + b * DIM + n0;
    if (tid < 128) { bias_s[tid] = bias[tid]; v_s[tid] = vvec[n0 + tid]; }

    const uint32_t sAu = smem_u32(sA8), sBu = smem_u32(sB8);
    int lr = tid >> 1, lh = tid & 1;

    auto load_chunk = [&](int kc) {
        int st = kc & 3;
        cp16(sAu + st * 4096 + lr * 32 + lh * 16,
             Ab + (size_t)lr * 512 + kc * 32 + lh * 16);
        cp16(sBu + st * 4096 + tid * 16, &g_wt8[MODE][kc][n0][0] + tid * 16);
        asm volatile("cp.async.commit_group;" ::: "memory");
    };

    float c[4][4][4];
    #pragma unroll
    for (int i = 0; i < 4; i++)
        #pragma unroll
        for (int j = 0; j < 4; j++)
            #pragma unroll
            for (int q = 0; q < 4; q++) c[i][j][q] = 0.f;

    uint32_t aBase = sAu + (warp_m * 64 + (lane >> 2)) * 32 + (lane & 3) * 8;
    uint32_t bBase = sBu + (warp_n * 32 + (lane >> 2)) * 32 + (lane & 3) * 8;

    load_chunk(0); load_chunk(1); load_chunk(2);

    #pragma unroll 1
    for (int kc = 0; kc < 16; kc++) {
        if (kc < 14)       asm volatile("cp.async.wait_group 2;" ::: "memory");
        else if (kc == 14) asm volatile("cp.async.wait_group 1;" ::: "memory");
        else               asm volatile("cp.async.wait_group 0;" ::: "memory");
        __syncthreads();
        if (kc + 3 < 16) load_chunk(kc + 3);

        int st = kc & 3;
        uint32_t af[4][4], bf[4][2];
        #pragma unroll
        for (int mf = 0; mf < 4; mf++) {
            uint32_t base = aBase + st * 4096 + mf * 512;
            lds64(af[mf][0], af[mf][2], base);
            lds64(af[mf][1], af[mf][3], base + 256);
        }
        #pragma unroll
        for (int nf = 0; nf < 4; nf++)
            lds64(bf[nf][0], bf[nf][1], bBase + st * 4096 + nf * 256);
        #pragma unroll
        for (int mf = 0; mf < 4; mf++)
            #pragma unroll
            for (int nf = 0; nf < 4; nf++)
                mma_fp8(c[mf][nf], af[mf][0], af[mf][1], af[mf][2], af[mf][3],
                        bf[nf][0], bf[nf][1]);
    }
    __syncthreads();

    int qr = lane >> 2, qc = lane & 3;
    #pragma unroll
    for (int mf = 0; mf < 4; mf++) {
        int r0 = warp_m * 64 + mf * 16 + qr;
        int r1 = r0 + 8;
        float s0 = 0.f, s1 = 0.f;
        #pragma unroll
        for (int nf = 0; nf < 4; nf++) {
            int nl = warp_n * 32 + nf * 8 + qc * 2;
            float f0 = c[mf][nf][0] * SCI, f1 = c[mf][nf][1] * SCI;
            float f2 = c[mf][nf][2] * SCI, f3 = c[mf][nf][3] * SCI;
            if (MODE == 0) {
                size_t base = ((size_t)b * NENT + m0) * (DIM / 2) + (n0 + nl) / 2;
                g_sidefeat[base + (size_t)r0 * (DIM / 2)] = bfp(f0, f1);
                g_sidefeat[base + (size_t)r1 * (DIM / 2)] = bfp(f2, f3);
            }
            s0 += tanh_fast(f0 + bias_s[nl]) * v_s[nl] + tanh_fast(f1 + bias_s[nl + 1]) * v_s[nl + 1];
            s1 += tanh_fast(f2 + bias_s[nl]) * v_s[nl] + tanh_fast(f3 + bias_s[nl + 1]) * v_s[nl + 1];
        }
        s0 += __shfl_xor_sync(0xffffffffu, s0, 1);
        s0 += __shfl_xor_sync(0xffffffffu, s0, 2);
        s1 += __shfl_xor_sync(0xffffffffu, s1, 1);
        s1 += __shfl_xor_sync(0xffffffffu, s1, 2);
        if (qc == 0) { sPart[r0 * 4 + warp_n] = s0; sPart[r1 * 4 + warp_n] = s1; }
    }
    __syncthreads();
    if (tid < 128) {
        float s = sPart[tid * 4] + sPart[tid * 4 + 1] + sPart[tid * 4 + 2] + sPart[tid * 4 + 3];
        float* spart = (MODE == 0) ? g_escore_part : g_score_part;
        spart[((size_t)blockIdx.x * BATCH + b) * R + m0 + tid] = s;
    }
}

// ---------------- LSTM: block = 8 h, loop all 64 b (W read once) -------------
__global__ void lstm_kernel(const float* __restrict__ x, const float* __restrict__ wih,
                            const float* __restrict__ bih, const float* __restrict__ bhh) {
    __shared__ float xT[64][65];
    __shared__ float wrow[3][8][64];
    int tid = threadIdx.x, wid = tid >> 5, lane = tid & 31;
    int h = blockIdx.x * 8 + wid;
    float ai[2] = {0.f, 0.f}, ag[2] = {0.f, 0.f}, ao[2] = {0.f, 0.f};
    #pragma unroll 1
    for (int cb = 0; cb < 8; cb++) {
        int k0 = cb * 64;
        __syncthreads();
        #pragma unroll
        for (int i = 0; i < 4; i++) {
            int bb = tid >> 2, kv = (tid & 3) + 4 * i;
            float4 v = *(const float4*)&x[bb * DIM + k0 + kv * 4];
            xT[kv * 4 + 0][bb] = v.x; xT[kv * 4 + 1][bb] = v.y;
            xT[kv * 4 + 2][bb] = v.z; xT[kv * 4 + 3][bb] = v.w;
        }
        #pragma unroll
        for (int i = 0; i < 6; i++) {
            int idx = tid + i * 256;
            int g = idx >> 9, rem = idx & 511, hh = rem >> 6, kk = rem & 63;
            int grow = (g == 0) ? 0 : (g == 1 ? 2 : 3);
            wrow[g][hh][kk] = wih[(size_t)(grow * 512 + blockIdx.x * 8 + hh) * DIM + k0 + kk];
        }
        __syncthreads();
        #pragma unroll 16
        for (int kk = 0; kk < 64; kk++) {
            float x0 = xT[kk][lane], x1 = xT[kk][lane + 32];
            float wi_ = wrow[0][wid][kk], wg_ = wrow[1][wid][kk], wo_ = wrow[2][wid][kk];
            ai[0] = fmaf(wi_, x0, ai[0]); ai[1] = fmaf(wi_, x1, ai[1]);
            ag[0] = fmaf(wg_, x0, ag[0]); ag[1] = fmaf(wg_, x1, ag[1]);
            ao[0] = fmaf(wo_, x0, ao[0]); ao[1] = fmaf(wo_, x1, ao[1]);
        }
    }
    float bi = bih[h] + bhh[h];
    float bg = bih[1024 + h] + bhh[1024 + h];
    float bo = bih[1536 + h] + bhh[1536 + h];
    #pragma unroll
    for (int j = 0; j < 2; j++) {
        int bb = lane + 32 * j;
        float ii = sigmoidf_(ai[j] + bi);
        float gg = tanhf(ag[j] + bg);
        float oo = sigmoidf_(ao[j] + bo);
        g_query[bb * DIM + h] = oo * tanhf(ii * gg);
    }
}

// ---------------- proj01: grid (64 htile, 2 mode, 2 bhalf) -------------------
__global__ void proj01_kernel() {
    __shared__ float xT[64][33];
    __shared__ float wrow[8][64];
    int tid = threadIdx.x, wid = tid >> 5, lane = tid & 31;
    int mode = blockIdx.y, bh = blockIdx.z;
    int h = blockIdx.x * 8 + wid;
    const float* W = g_wqt[mode];
    float acc = 0.f;
    #pragma unroll 1
    for (int cb = 0; cb < 8; cb++) {
        int k0 = cb * 64;
        __syncthreads();
        {
            int bb = tid >> 3, kq = (tid & 7) * 2;
            float4 v0 = *(const float4*)&g_query[(bh * 32 + bb) * DIM + k0 + kq * 4];
            float4 v1 = *(const float4*)&g_query[(bh * 32 + bb) * DIM + k0 + kq * 4 + 4];
            xT[kq * 4 + 0][bb] = v0.x; xT[kq * 4 + 1][bb] = v0.y;
            xT[kq * 4 + 2][bb] = v0.z; xT[kq * 4 + 3][bb] = v0.w;
            xT[kq * 4 + 4][bb] = v1.x; xT[kq * 4 + 5][bb] = v1.y;
            xT[kq * 4 + 6][bb] = v1.z; xT[kq * 4 + 7][bb] = v1.w;
        }
        #pragma unroll
        for (int i = 0; i < 2; i++) {
            int idx = tid + i * 256;
            int hh = idx >> 6, kk = idx & 63;
            wrow[hh][kk] = W[(size_t)(blockIdx.x * 8 + hh) * DIM + k0 + kk];
        }
        __syncthreads();
        #pragma unroll 16
        for (int kk = 0; kk < 64; kk++)
            acc = fmaf(wrow[wid][kk], xT[kk][lane], acc);
    }
    ((mode == 0) ? g_qs : g_qa)[(bh * 32 + lane) * DIM + h] = acc;
}

// ---------------- proj2: bias = qa + ctx @ ws; grid (64, 2 bhalf) ------------
__global__ void proj2_kernel() {
    __shared__ float xT[64][33];
    __shared__ float wrow[8][64];
    int tid = threadIdx.x, wid = tid >> 5, lane = tid & 31;
    int bh = blockIdx.y;
    int h = blockIdx.x * 8 + wid;
    const float* W = g_wqt[2];
    float acc = 0.f;
    #pragma unroll 1
    for (int cb = 0; cb < 8; cb++) {
        int k0 = cb * 64;
        __syncthreads();
        {
            int bb = tid >> 3, kq = (tid & 7) * 2;
            float4 v0 = *(const float4*)&g_ctx[(bh * 32 + bb) * DIM + k0 + kq * 4];
            float4 v1 = *(const float4*)&g_ctx[(bh * 32 + bb) * DIM + k0 + kq * 4 + 4];
            xT[kq * 4 + 0][bb] = v0.x; xT[kq * 4 + 1][bb] = v0.y;
            xT[kq * 4 + 2][bb] = v0.z; xT[kq * 4 + 3][bb] = v0.w;
            xT[kq * 4 + 4][bb] = v1.x; xT[kq * 4 + 5][bb] = v1.y;
            xT[kq * 4 + 6][bb] = v1.z; xT[kq * 4 + 7][bb] = v1.w;
        }
        #pragma unroll
        for (int i = 0; i < 2; i++) {
            int idx = tid + i * 256;
            int hh = idx >> 6, kk = idx & 63;
            wrow[hh][kk] = W[(size_t)(blockIdx.x * 8 + hh) * DIM + k0 + kk];
        }
        __syncthreads();
        #pragma unroll 16
        for (int kk = 0; kk < 64; kk++)
            acc = fmaf(wrow[wid][kk], xT[kk][lane], acc);
    }
    int bb = bh * 32 + lane;
    g_bias[bb * DIM + h] = g_qa[bb * DIM + h] + acc;
}

// ---------------- masked softmax over entities -> g_attn ---------------------
__global__ void softmax_kernel(const int* __restrict__ entity_nums) {
    int b = blockIdx.x, tid = threadIdx.x;
    __shared__ float red[8];
    int n = entity_nums[b];
    float v = g_escore_part[(0 * BATCH + b) * NENT + tid]
            + g_escore_part[(1 * BATCH + b) * NENT + tid]
            + g_escore_part[(2 * BATCH + b) * NENT + tid]
            + g_escore_part[(3 * BATCH + b) * NENT + tid];
    if (tid >= n) v = NEGV;
    float m = v;
    #pragma unroll
    for (int o = 16; o; o >>= 1) m = fmaxf(m, __shfl_xor_sync(0xffffffffu, m, o));
    if ((tid & 31) == 0) red[tid >> 5] = m;
    __syncthreads();
    float M = red[0];
    #pragma unroll
    for (int i = 1; i < 8; i++) M = fmaxf(M, red[i]);
    __syncthreads();
    float e = expf(v - M);
    float s = warp_sum(e);
    if ((tid & 31) == 0) red[tid >> 5] = s;
    __syncthreads();
    float S = red[0];
    #pragma unroll
    for (int i = 1; i < 8; i++) S += red[i];
    g_attn[b * NENT + tid] = e / S;
}

// ---------------- ctx from bf16 sidefeat -------------------------------------
__global__ void ctx_kernel() {
    int b = blockIdx.y;
    int h2 = blockIdx.x * 128 + threadIdx.x;
    __shared__ float attn[NENT];
    attn[threadIdx.x] = g_attn[b * NENT + threadIdx.x];
    attn[threadIdx.x + 128] = g_attn[b * NENT + 128 + threadIdx.x];
    __syncthreads();
    const __nv_bfloat162* fb = g_sidefeat + (size_t)b * NENT * (DIM / 2) + h2;
    float a0 = 0.f, a1 = 0.f;
    #pragma unroll 8
    for (int e = 0; e < NENT; e++) {
        __nv_bfloat162 f = fb[(size_t)e * (DIM / 2)];
        a0 = fmaf(attn[e], __bfloat162float(f.x), a0);
        a1 = fmaf(attn[e], __bfloat162float(f.y), a1);
    }
    g_ctx[b * DIM + 2 * h2]     = a0;
    g_ctx[b * DIM + 2 * h2 + 1] = a1;
}

// ---------------- finalize ----------------------------------------------------
__global__ void finalize_kernel(const int* __restrict__ sent_nums, float* __restrict__ out) {
    int i = blockIdx.x * 256 + threadIdx.x;
    int b = i >> 10, s = i & 1023;
    float v = g_score_part[(0 * BATCH + b) * NSENT + s]
            + g_score_part[(1 * BATCH + b) * NSENT + s]
            + g_score_part[(2 * BATCH + b) * NSENT + s]
            + g_score_part[(3 * BATCH + b) * NSENT + s];
    out[i] = (s < sent_nums[b]) ? v : NEGV;
}

// ---------------- launch ------------------------------------------------------
extern "C" void kernel_launch(void* const* d_in, const int* in_sizes, int n_in,
                              void* d_out, int out_size) {
    const float* sent_mem    = (const float*)d_in[0];
    const float* entity_mem  = (const float*)d_in[1];
    const float* ptr_in      = (const float*)d_in[2];
    const int*   sent_nums   = (const int*)d_in[3];
    const int*   entity_nums = (const int*)d_in[4];
    const float* lstm_w_ih   = (const float*)d_in[5];
    const float* lstm_b_ih   = (const float*)d_in[7];
    const float* lstm_b_hh   = (const float*)d_in[8];
    const float* attn_wm     = (const float*)d_in[9];
    const float* attn_wq     = (const float*)d_in[10];
    const float* attn_v      = (const float*)d_in[11];
    const float* side_wm     = (const float*)d_in[12];
    const float* side_wq     = (const float*)d_in[13];
    const float* side_v      = (const float*)d_in[14];
    const float* attn_ws     = (const float*)d_in[15];
    float* out = (float*)d_out;

    static cudaStream_t s2;
    static cudaEvent_t ev_fork, ev_join;
    static bool init_done = false;
    if (!init_done) {
        cudaStreamCreateWithFlags(&s2, cudaStreamNonBlocking);
        cudaEventCreateWithFlags(&ev_fork, cudaEventDisableTiming);
        cudaEventCreateWithFlags(&ev_join, cudaEventDisableTiming);
        init_done = true;
    }

    uint8_t* sent8; cudaGetSymbolAddress((void**)&sent8, g_sent8);
    uint8_t* ent8;  cudaGetSymbolAddress((void**)&ent8, g_ent8);

    // fork: big sent conversion runs on s2, overlapping the entity chain
    cudaEventRecord(ev_fork, 0);
    cudaStreamWaitEvent(s2, ev_fork, 0);
    cvt_a8<<<4096, 256, 0, s2>>>(sent_mem, sent8);
    cudaEventRecord(ev_join, s2);

    // main (capture) stream: entity chain
    prepack_w8<<<dim3(16, 16, 2), dim3(32, 32)>>>(side_wm, attn_wm);
    prepack_wt<<<dim3(16, 16, 3), dim3(32, 32)>>>(side_wq, attn_wq, attn_ws);
    lstm_kernel<<<64, 256>>>(ptr_in, lstm_w_ih, lstm_b_ih, lstm_b_hh);
    proj01_kernel<<<dim3(64, 2, 2), 256>>>();
    cvt_a8<<<1024, 256>>>(entity_mem, ent8);
    gemm_mma<0><<<dim3(4, 2, BATCH), 256>>>(side_v);
    softmax_kernel<<<BATCH, 256>>>(entity_nums);
    ctx_kernel<<<dim3(2, BATCH), 128>>>();
    proj2_kernel<<<dim3(64, 2), 256>>>();

    // join: sent fp8 must be ready before the big GEMM
    cudaStreamWaitEvent(0, ev_join, 0);
    gemm_mma<1><<<dim3(4, 8, BATCH), 256>>>(sent_mem ? attn_v : attn_v);
    finalize_kernel<<<BATCH * NSENT / 256, 256>>>(sent_nums, out);
}